// round 3
// baseline (speedup 1.0000x reference)
#include <cuda_runtime.h>
#include <cstdint>

#define BATCHES 64
#define NPTS    (1<<18)
#define NCL     8
#define NITER   10
#define CAND_CAP 1024
#define K2_THRESH (1u<<22)

__device__ unsigned g_key1[(size_t)BATCHES * NPTS];
__device__ unsigned long long g_cand[BATCHES * CAND_CAP];
__device__ int g_cand_cnt[BATCHES];
__device__ uint2 g_sub1[BATCHES], g_sub2[BATCHES];
__device__ float g_cent[BATCHES * NCL * 3];
__device__ float g_sums[BATCHES * NCL * 4];
__device__ int g_done[BATCHES];

// ---------------- packed f32x2 helpers ----------------
__device__ __forceinline__ unsigned long long pk(float lo, float hi) {
  unsigned long long r;
  asm("mov.b64 %0, {%1,%2};" : "=l"(r) : "f"(lo), "f"(hi));
  return r;
}
__device__ __forceinline__ void upk(unsigned long long v, unsigned &lo, unsigned &hi) {
  asm("mov.b64 {%0,%1}, %2;" : "=r"(lo), "=r"(hi) : "l"(v));
}
__device__ __forceinline__ unsigned long long f2fma(unsigned long long a,
                                                    unsigned long long b,
                                                    unsigned long long c) {
  unsigned long long d;
  asm("fma.rn.f32x2 %0, %1, %2, %3;" : "=l"(d) : "l"(a), "l"(b), "l"(c));
  return d;
}
__device__ __forceinline__ unsigned long long f2add(unsigned long long a,
                                                    unsigned long long b) {
  unsigned long long d;
  asm("add.rn.f32x2 %0, %1, %2;" : "=l"(d) : "l"(a), "l"(b));
  return d;
}

// ---------------- Threefry-2x32 (JAX-compatible) ----------------
__device__ __forceinline__ void tf2x32(unsigned k0, unsigned k1,
                                       unsigned x0, unsigned x1,
                                       unsigned &o0, unsigned &o1) {
  unsigned k2 = k0 ^ k1 ^ 0x1BD11BDAu;
  x0 += k0; x1 += k1;
#define TF_R(r) { x0 += x1; x1 = __funnelshift_l(x1, x1, (r)); x1 ^= x0; }
  TF_R(13) TF_R(15) TF_R(26) TF_R(6)  x0 += k1; x1 += k2 + 1u;
  TF_R(17) TF_R(29) TF_R(16) TF_R(24) x0 += k2; x1 += k0 + 2u;
  TF_R(13) TF_R(15) TF_R(26) TF_R(6)  x0 += k0; x1 += k1 + 3u;
  TF_R(17) TF_R(29) TF_R(16) TF_R(24) x0 += k1; x1 += k2 + 4u;
  TF_R(13) TF_R(15) TF_R(26) TF_R(6)  x0 += k2; x1 += k0 + 5u;
#undef TF_R
  o0 = x0; o1 = x1;
}

__global__ void k_init() {
  int b = threadIdx.x;
  if (b >= BATCHES) return;
  unsigned a0, a1, n0, n1, s0, s1;
  tf2x32(0u, 42u, 0u, (unsigned)b, a0, a1);
  tf2x32(a0, a1, 0u, 0u, n0, n1);
  tf2x32(a0, a1, 0u, 1u, s0, s1);
  g_sub1[b] = make_uint2(s0, s1);
  tf2x32(n0, n1, 0u, 1u, s0, s1);
  g_sub2[b] = make_uint2(s0, s1);
  g_cand_cnt[b] = 0;
  g_done[b] = 0;
}

__global__ void k_gen() {
  unsigned stride = gridDim.x * blockDim.x;
  for (unsigned idx = blockIdx.x * blockDim.x + threadIdx.x;
       idx < (unsigned)BATCHES * NPTS; idx += stride) {
    int b = idx >> 18;
    unsigned i = idx & (NPTS - 1);
    uint2 s1 = g_sub1[b], s2 = g_sub2[b];
    unsigned y0, y1;
    tf2x32(s1.x, s1.y, 0u, i, y0, y1);
    g_key1[idx] = y0 ^ y1;
    tf2x32(s2.x, s2.y, 0u, i, y0, y1);
    unsigned k2v = y0 ^ y1;
    if (k2v < K2_THRESH) {
      int slot = atomicAdd(&g_cand_cnt[b], 1);
      if (slot < CAND_CAP)
        g_cand[b * CAND_CAP + slot] = ((unsigned long long)k2v << 32) | i;
    }
  }
}

__global__ void __launch_bounds__(1024) k_select(const float* __restrict__ in) {
  int b = blockIdx.x;
  int t = threadIdx.x;
  int lane = t & 31, wid = t >> 5;
  __shared__ unsigned long long s_cand[CAND_CAP];
  __shared__ unsigned s_whist[32][256];
  __shared__ unsigned s_h[256];
  __shared__ unsigned long long s_list[8][64];
  __shared__ int s_lcnt[8];
  __shared__ int s_rank[8];
  __shared__ unsigned s_pfx[8];
  __shared__ unsigned s_v[8];
  __shared__ unsigned long long s_min;

  int cnt = g_cand_cnt[b]; if (cnt > CAND_CAP) cnt = CAND_CAP;
  s_cand[t] = (t < cnt) ? g_cand[b * CAND_CAP + t] : ~0ull;
  __syncthreads();
  for (int k = 0; k < 8; ++k) {
    if (t == 0) s_min = ~0ull;
    __syncthreads();
    atomicMin(&s_min, s_cand[t]);
    __syncthreads();
    unsigned long long m = s_min;
    if (t == 0) { s_rank[k] = (int)(m & 0xffffffffull); s_pfx[k] = 0u; s_lcnt[k] = 0; }
    if (s_cand[t] == m) s_cand[t] = ~0ull;
    __syncthreads();
  }

  const unsigned* __restrict__ keyp = g_key1 + (size_t)b * NPTS;

  for (int i = lane; i < 256; i += 32) s_whist[wid][i] = 0u;
  __syncthreads();
  for (int i = t; i < NPTS; i += 1024) {
    unsigned k = keyp[i];
    unsigned bt = k >> 24;
    unsigned mm = __match_any_sync(0xffffffffu, bt);
    if (lane == (__ffs(mm) - 1)) s_whist[wid][bt] += __popc(mm);
  }
  __syncthreads();
  if (t < 256) {
    unsigned s = 0;
    for (int w = 0; w < 32; ++w) s += s_whist[w][t];
    s_h[t] = s;
  }
  __syncthreads();
  if (t < 8) {
    int r = s_rank[t], cum = 0, d = 0;
    for (; d < 256; ++d) { int h = (int)s_h[d]; if (cum + h > r) break; cum += h; }
    s_rank[t] = r - cum; s_pfx[t] = (unsigned)d << 24;
  }
  __syncthreads();

  for (int i = t; i < 8 * 256; i += 1024) (&s_whist[0][0])[i] = 0u;
  __syncthreads();
  unsigned pf[8];
  #pragma unroll
  for (int j = 0; j < 8; ++j) pf[j] = s_pfx[j];
  for (int i = t; i < NPTS; i += 1024) {
    unsigned k = keyp[i];
    unsigned top = k & 0xFF000000u;
    #pragma unroll
    for (int j = 0; j < 8; ++j)
      if (top == pf[j]) atomicAdd(&s_whist[j][(k >> 16) & 255u], 1u);
  }
  __syncthreads();
  if (t < 8) {
    int r = s_rank[t], cum = 0, d = 0;
    for (; d < 256; ++d) { int h = (int)s_whist[t][d]; if (cum + h > r) break; cum += h; }
    s_rank[t] = r - cum; s_pfx[t] |= (unsigned)d << 16;
  }
  __syncthreads();

  #pragma unroll
  for (int j = 0; j < 8; ++j) pf[j] = s_pfx[j];
  for (int i = t; i < NPTS; i += 1024) {
    unsigned k = keyp[i];
    unsigned top = k & 0xFFFF0000u;
    #pragma unroll
    for (int j = 0; j < 8; ++j)
      if (top == pf[j]) {
        int s = atomicAdd(&s_lcnt[j], 1);
        if (s < 64) s_list[j][s] = ((unsigned long long)(k & 0xFFFFu) << 32) | (unsigned)i;
      }
  }
  __syncthreads();
  if (t < 8) {
    int n = s_lcnt[t]; if (n > 64) n = 64;
    int r = s_rank[t];
    unsigned long long last = 0ull; bool first = true;
    for (int step = 0; step <= r && step < n; ++step) {
      unsigned long long mn = ~0ull;
      for (int q = 0; q < n; ++q) {
        unsigned long long v = s_list[t][q];
        if ((first || v > last) && v < mn) mn = v;
      }
      last = mn; first = false;
    }
    s_v[t] = (unsigned)(last & 0xffffffffull);
  }
  __syncthreads();
  if (t < 8) {
    const float* px = in + ((size_t)b * NPTS + s_v[t]) * 3;
    float* c = g_cent + (b * NCL + t) * 3;
    c[0] = px[0]; c[1] = px[1]; c[2] = px[2];
  }
  if (t < 32) g_sums[b * 32 + t] = 0.f;
}

// ------- Lloyd assignment + sums + fused centroid update (last block) -------
__global__ void __launch_bounds__(256) k_assign(const float* __restrict__ in,
                                                float* __restrict__ out,
                                                int wout) {
  int b   = blockIdx.x >> 5;
  int blk = blockIdx.x & 31;
  int tid = threadIdx.x;
  __shared__ float4 s_st[768];                        // 1024-pt stage (12 KB)
  __shared__ unsigned long long s_acc[8][2][256];     // [cl][xy|zc][tid] (32 KB)

  // packed constants: pair p covers clusters (2p, 2p+1)
  unsigned long long N0[4], N1[4], N2[4], BB[4];
  const float* cent = g_cent + b * 24;
  #pragma unroll
  for (int p = 0; p < 4; ++p) {
    float a0 = cent[(2*p)*3+0], a1 = cent[(2*p)*3+1], a2 = cent[(2*p)*3+2];
    float c0 = cent[(2*p+1)*3+0], c1 = cent[(2*p+1)*3+1], c2 = cent[(2*p+1)*3+2];
    N0[p] = pk(-2.f*a0, -2.f*c0);
    N1[p] = pk(-2.f*a1, -2.f*c1);
    N2[p] = pk(-2.f*a2, -2.f*c2);
    // +6 keeps all scores positive (x.c <= 3) so uint compare == float compare
    BB[p] = pk(a0*a0+a1*a1+a2*a2 + 6.f, c0*c0+c1*c1+c2*c2 + 6.f);
  }
  unsigned long long* accb = &s_acc[0][0][tid];
  for (int i = tid; i < 8*2*256; i += 256) (&s_acc[0][0][0])[i] = 0ull;

  const float4* gp = (const float4*)in + (size_t)b * (NPTS*3/4) + (size_t)blk * 6144;
  for (int ch = 0; ch < 8; ++ch) {
    __syncthreads();
    const float4* src = gp + ch * 768;
    s_st[tid]       = src[tid];
    s_st[tid + 256] = src[tid + 256];
    s_st[tid + 512] = src[tid + 512];
    __syncthreads();
    float4 A = s_st[3*tid], B4 = s_st[3*tid+1], C = s_st[3*tid+2];
    float qx[4] = {A.x, A.w, B4.z, C.y};
    float qy[4] = {A.y, B4.x, B4.w, C.z};
    float qz[4] = {A.z, B4.y, C.x,  C.w};
    #pragma unroll
    for (int q = 0; q < 4; ++q) {
      float x0 = qx[q], x1 = qy[q], x2 = qz[q];
      unsigned long long xp0 = pk(x0,x0), xp1 = pk(x1,x1), xp2 = pk(x2,x2);
      unsigned long long s0 = f2fma(xp2, N2[0], f2fma(xp1, N1[0], f2fma(xp0, N0[0], BB[0])));
      unsigned long long s1 = f2fma(xp2, N2[1], f2fma(xp1, N1[1], f2fma(xp0, N0[1], BB[1])));
      unsigned long long s2 = f2fma(xp2, N2[2], f2fma(xp1, N1[2], f2fma(xp0, N0[2], BB[2])));
      unsigned long long s3 = f2fma(xp2, N2[3], f2fma(xp1, N1[3], f2fma(xp0, N0[3], BB[3])));
      unsigned d0,d1,d2,d3,d4,d5,d6,d7;
      upk(s0,d0,d1); upk(s1,d2,d3); upk(s2,d4,d5); upk(s3,d6,d7);
      // index in low 3 bits; distances positive -> uint order == float order
      unsigned u0 =  d0 & 0xFFFFFFF8u;
      unsigned u1 = (d1 & 0xFFFFFFF8u) | 1u;
      unsigned u2 = (d2 & 0xFFFFFFF8u) | 2u;
      unsigned u3 = (d3 & 0xFFFFFFF8u) | 3u;
      unsigned u4 = (d4 & 0xFFFFFFF8u) | 4u;
      unsigned u5 = (d5 & 0xFFFFFFF8u) | 5u;
      unsigned u6 = (d6 & 0xFFFFFFF8u) | 6u;
      unsigned u7 = (d7 & 0xFFFFFFF8u) | 7u;
      unsigned m = min(min(min(u0,u1),min(u2,u3)), min(min(u4,u5),min(u6,u7)));
      unsigned bi = m & 7u;
      unsigned long long* a = accb + bi * 512;          // cluster stride = 2*256
      a[0]   = f2add(a[0],   pk(x0, x1));
      a[256] = f2add(a[256], pk(x2, 1.f));
    }
  }
  __syncthreads();

  int w = tid >> 5, lane = tid & 31;   // warp w reduces cluster w
  unsigned long long rxy = 0ull, rzc = 0ull;
  #pragma unroll
  for (int k = 0; k < 8; ++k) {
    rxy = f2add(rxy, s_acc[w][0][lane + 32*k]);
    rzc = f2add(rzc, s_acc[w][1][lane + 32*k]);
  }
  unsigned ax, ay, az, ac;
  upk(rxy, ax, ay); upk(rzc, az, ac);
  float fx = __uint_as_float(ax), fy = __uint_as_float(ay);
  float fz = __uint_as_float(az), fc = __uint_as_float(ac);
  #pragma unroll
  for (int o = 16; o; o >>= 1) {
    fx += __shfl_down_sync(0xffffffffu, fx, o);
    fy += __shfl_down_sync(0xffffffffu, fy, o);
    fz += __shfl_down_sync(0xffffffffu, fz, o);
    fc += __shfl_down_sync(0xffffffffu, fc, o);
  }
  if (lane == 0) {
    float* gs = g_sums + b * 32 + w * 4;
    atomicAdd(gs+0, fx); atomicAdd(gs+1, fy);
    atomicAdd(gs+2, fz); atomicAdd(gs+3, fc);
    __threadfence();
  }
  __syncthreads();

  if (tid == 0) {
    int old = atomicAdd(&g_done[b], 1);
    if (old == 31) {                      // last block of this batch: do update
      __threadfence();
      float* gs = g_sums + b * 32;
      float* cc = g_cent + b * 24;
      #pragma unroll
      for (int c = 0; c < 8; ++c) {
        float sx = gs[c*4+0], sy = gs[c*4+1], sz = gs[c*4+2], cn = gs[c*4+3];
        float ox, oy, oz;
        if (cn > 0.f) { ox = sx/cn; oy = sy/cn; oz = sz/cn; }
        else          { ox = cc[c*3]; oy = cc[c*3+1]; oz = cc[c*3+2]; }
        cc[c*3] = ox; cc[c*3+1] = oy; cc[c*3+2] = oz;
        gs[c*4] = 0.f; gs[c*4+1] = 0.f; gs[c*4+2] = 0.f; gs[c*4+3] = 0.f;
        if (wout) {
          out[b*24 + c*3 + 0] = ox;
          out[b*24 + c*3 + 1] = oy;
          out[b*24 + c*3 + 2] = oz;
        }
      }
      g_done[b] = 0;                      // self-clean for next launch / replay
    }
  }
}

extern "C" void kernel_launch(void* const* d_in, const int* in_sizes, int n_in,
                              void* d_out, int out_size) {
  const float* in = (const float*)d_in[0];
  float* out = (float*)d_out;
  k_init<<<1, 64>>>();
  k_gen<<<4096, 256>>>();
  k_select<<<BATCHES, 1024>>>(in);
  for (int it = 0; it < NITER; ++it)
    k_assign<<<BATCHES * 32, 256>>>(in, out, it == NITER - 1 ? 1 : 0);
}